// round 5
// baseline (speedup 1.0000x reference)
#include <cuda_runtime.h>
#include <cuda_bf16.h>
#include <cstdint>

#define B_DIM   512
#define IN_DIM  4096
#define OUT_DIM 11008

#define BM 128
#define BN 128
#define BK 32
#define NK (IN_DIM / BK)   // 128 k-chunks
#define STAGES 5
#define THREADS 256

#define ROWPAD 80                       // 64B data + 16B pad per row (bank-conflict-free)
#define TILE_B (128 * ROWPAD)           // 10240 B per tile
#define STAGE_B (4 * TILE_B)            // 40960 B per stage (Ahi,Alo,Bhi,Blo)
#define SMEM_TOTAL (STAGES * STAGE_B)   // 204800 B

// ---------------- device scratch (static device arrays are allowed) ----------------
__device__ __nv_bfloat16 g_whi[(size_t)OUT_DIM * IN_DIM];
__device__ __nv_bfloat16 g_wlo[(size_t)OUT_DIM * IN_DIM];
__device__ __nv_bfloat16 g_xhi[(size_t)B_DIM * IN_DIM];
__device__ __nv_bfloat16 g_xlo[(size_t)B_DIM * IN_DIM];

// ---------------- PTX helpers (plain sm_80+ features only) -------------------------
__device__ __forceinline__ uint32_t smem_u32(const void* p) {
    uint32_t a;
    asm("{ .reg .u64 t; cvta.to.shared.u64 t, %1; cvt.u32.u64 %0, t; }" : "=r"(a) : "l"(p));
    return a;
}

__device__ __forceinline__ void cp16(uint32_t s, const void* g) {
    asm volatile("cp.async.cg.shared.global [%0], [%1], 16;" :: "r"(s), "l"(g));
}
__device__ __forceinline__ void cp_commit() {
    asm volatile("cp.async.commit_group;" ::: "memory");
}
template <int N>
__device__ __forceinline__ void cp_wait() {
    asm volatile("cp.async.wait_group %0;" :: "n"(N) : "memory");
}

__device__ __forceinline__ void ldsm4(uint32_t* r, uint32_t addr) {
    asm volatile("ldmatrix.sync.aligned.m8n8.x4.shared.b16 {%0,%1,%2,%3}, [%4];"
                 : "=r"(r[0]), "=r"(r[1]), "=r"(r[2]), "=r"(r[3]) : "r"(addr));
}

__device__ __forceinline__ void mma_bf16(float* d, const uint32_t* a, const uint32_t* b) {
    asm volatile("mma.sync.aligned.m16n8k16.row.col.f32.bf16.bf16.f32 "
                 "{%0,%1,%2,%3}, {%4,%5,%6,%7}, {%8,%9}, {%0,%1,%2,%3};"
                 : "+f"(d[0]), "+f"(d[1]), "+f"(d[2]), "+f"(d[3])
                 : "r"(a[0]), "r"(a[1]), "r"(a[2]), "r"(a[3]), "r"(b[0]), "r"(b[1]));
}

// ---------------- Kernel 1: dequant W -> bf16 hi/lo (256-entry exp LUT) ------------
__global__ void dequant_kernel(const int* __restrict__ stored, const int* __restrict__ sgn,
                               const float* __restrict__ lmin_p, const float* __restrict__ lmax_p) {
    __shared__ uint32_t lut[256];
    float lmin = *lmin_p;
    float kf = (*lmax_p - lmin) * (1.0f / 254.0f);
    for (int s = threadIdx.x; s < 256; s += blockDim.x) {
        float w = expf(lmin + (float)(255 - s) * kf);
        __nv_bfloat16 hb = __float2bfloat16(w);
        float fh = __bfloat162float(hb);
        __nv_bfloat16 lb = __float2bfloat16(w - fh);
        lut[s] = ((uint32_t)__bfloat16_as_ushort(hb) << 16) | (uint32_t)__bfloat16_as_ushort(lb);
    }
    __syncthreads();

    const int4* st4 = (const int4*)stored;
    const int4* sg4 = (const int4*)sgn;
    ushort4* whi4 = (ushort4*)g_whi;
    ushort4* wlo4 = (ushort4*)g_wlo;
    size_t nq = (size_t)OUT_DIM * IN_DIM / 4;
    for (size_t i = (size_t)blockIdx.x * blockDim.x + threadIdx.x; i < nq;
         i += (size_t)gridDim.x * blockDim.x) {
        int4 s = st4[i];
        int4 g = sg4[i];
        uint32_t p0 = lut[s.x & 255] ^ (g.x < 0 ? 0x80008000u : 0u);
        uint32_t p1 = lut[s.y & 255] ^ (g.y < 0 ? 0x80008000u : 0u);
        uint32_t p2 = lut[s.z & 255] ^ (g.z < 0 ? 0x80008000u : 0u);
        uint32_t p3 = lut[s.w & 255] ^ (g.w < 0 ? 0x80008000u : 0u);
        whi4[i] = make_ushort4((unsigned short)(p0 >> 16), (unsigned short)(p1 >> 16),
                               (unsigned short)(p2 >> 16), (unsigned short)(p3 >> 16));
        wlo4[i] = make_ushort4((unsigned short)(p0 & 0xffff), (unsigned short)(p1 & 0xffff),
                               (unsigned short)(p2 & 0xffff), (unsigned short)(p3 & 0xffff));
    }
}

// ---------------- Kernel 2: split x -> bf16 hi/lo ----------------------------------
__global__ void xsplit_kernel(const float* __restrict__ x) {
    const float4* x4 = (const float4*)x;
    ushort4* xh = (ushort4*)g_xhi;
    ushort4* xl = (ushort4*)g_xlo;
    size_t n4 = (size_t)B_DIM * IN_DIM / 4;
    for (size_t i = (size_t)blockIdx.x * blockDim.x + threadIdx.x; i < n4;
         i += (size_t)gridDim.x * blockDim.x) {
        float4 v = x4[i];
        float vv[4] = {v.x, v.y, v.z, v.w};
        unsigned short h[4], l[4];
#pragma unroll
        for (int j = 0; j < 4; j++) {
            __nv_bfloat16 hb = __float2bfloat16(vv[j]);
            float fh = __bfloat162float(hb);
            h[j] = __bfloat16_as_ushort(hb);
            l[j] = __bfloat16_as_ushort(__float2bfloat16(vv[j] - fh));
        }
        xh[i] = make_ushort4(h[0], h[1], h[2], h[3]);
        xl[i] = make_ushort4(l[0], l[1], l[2], l[3]);
    }
}

// ---------------- Kernel 3: pipelined mma.sync bf16 GEMM + epilogue ----------------
// 3-term split: y = x_hi*w_hi + x_hi*w_lo + x_lo*w_hi  (lo*lo dropped, ~2^-18 rel)
__global__ void __launch_bounds__(THREADS, 1)
gemm_kernel(float* __restrict__ out, const float* __restrict__ scale,
            const float* __restrict__ bias) {
    extern __shared__ char smem[];
    const uint32_t sb = smem_u32(smem);
    const int tid = threadIdx.x;
    const int lane = tid & 31, wid = tid >> 5;
    const int nb = blockIdx.x * BN, mb = blockIdx.y * BM;
    const int warp_m = (wid & 3) * 32, warp_n = (wid >> 2) * 64;

    const char* gAh = (const char*)(g_xhi + (size_t)mb * IN_DIM);
    const char* gAl = (const char*)(g_xlo + (size_t)mb * IN_DIM);
    const char* gBh = (const char*)(g_whi + (size_t)nb * IN_DIM);
    const char* gBl = (const char*)(g_wlo + (size_t)nb * IN_DIM);

    // cp.async mapping: thread -> (row = tid/2, 32B half = tid%2); 2x16B per tile
    const int lrow = tid >> 1;
    const int lc = (tid & 1) * 32;

    // ldmatrix base offsets
    // A x4: lanes 0-7:(m0-7,k0-7) 8-15:(m8-15,k0-7) 16-23:(m0-7,k8-15) 24-31:(m8-15,k8-15)
    const uint32_t a_off = (uint32_t)(warp_m + (lane & 15)) * ROWPAD + ((lane >> 4) * 16);
    // B x4 over two n8-frags: n = (lane&7) + ((lane>>4)&1)*8, kbyte = ((lane>>3)&1)*16
    const uint32_t b_off =
        (uint32_t)(warp_n + (lane & 7) + ((lane >> 4) & 1) * 8) * ROWPAD + (((lane >> 3) & 1) * 16);

    float acc[2][8][4];
#pragma unroll
    for (int i = 0; i < 2; i++)
#pragma unroll
        for (int j = 0; j < 8; j++)
#pragma unroll
            for (int c = 0; c < 4; c++) acc[i][j][c] = 0.0f;

    auto load_stage = [&](int s, int k) {
        size_t go = (size_t)lrow * (IN_DIM * 2) + (size_t)k * (BK * 2) + lc;
        uint32_t so = sb + s * STAGE_B + (uint32_t)lrow * ROWPAD + lc;
        cp16(so, gAh + go);
        cp16(so + 16, gAh + go + 16);
        cp16(so + TILE_B, gAl + go);
        cp16(so + TILE_B + 16, gAl + go + 16);
        cp16(so + 2 * TILE_B, gBh + go);
        cp16(so + 2 * TILE_B + 16, gBh + go + 16);
        cp16(so + 3 * TILE_B, gBl + go);
        cp16(so + 3 * TILE_B + 16, gBl + go + 16);
    };

    // Term-outer compute: load ALL frags for a k16 step, then 48 MMAs with
    // accumulator-reuse distance 16 (covers HMMA latency).
    auto compute_stage = [&](int s) {
        uint32_t st = sb + s * STAGE_B;
        uint32_t aH = st + a_off, aL = st + TILE_B + a_off;
        uint32_t bH = st + 2 * TILE_B + b_off, bL = st + 3 * TILE_B + b_off;
#pragma unroll
        for (int s16 = 0; s16 < 2; s16++) {
            uint32_t kb = s16 * 32;
            uint32_t ah[2][4], al[2][4], bh[4][4], bl[4][4];
            ldsm4(ah[0], aH + kb);
            ldsm4(ah[1], aH + 16 * ROWPAD + kb);
            ldsm4(al[0], aL + kb);
            ldsm4(al[1], aL + 16 * ROWPAD + kb);
#pragma unroll
            for (int nblk = 0; nblk < 4; nblk++) ldsm4(bh[nblk], bH + nblk * 16 * ROWPAD + kb);
#pragma unroll
            for (int nblk = 0; nblk < 4; nblk++) ldsm4(bl[nblk], bL + nblk * 16 * ROWPAD + kb);

            // term 1: x_hi * w_hi
#pragma unroll
            for (int nblk = 0; nblk < 4; nblk++)
#pragma unroll
                for (int mt = 0; mt < 2; mt++) {
                    mma_bf16(acc[mt][2 * nblk], ah[mt], bh[nblk]);
                    mma_bf16(acc[mt][2 * nblk + 1], ah[mt], bh[nblk] + 2);
                }
            // term 2: x_hi * w_lo
#pragma unroll
            for (int nblk = 0; nblk < 4; nblk++)
#pragma unroll
                for (int mt = 0; mt < 2; mt++) {
                    mma_bf16(acc[mt][2 * nblk], ah[mt], bl[nblk]);
                    mma_bf16(acc[mt][2 * nblk + 1], ah[mt], bl[nblk] + 2);
                }
            // term 3: x_lo * w_hi
#pragma unroll
            for (int nblk = 0; nblk < 4; nblk++)
#pragma unroll
                for (int mt = 0; mt < 2; mt++) {
                    mma_bf16(acc[mt][2 * nblk], al[mt], bh[nblk]);
                    mma_bf16(acc[mt][2 * nblk + 1], al[mt], bh[nblk] + 2);
                }
        }
    };

    // prologue: fill STAGES-1 stages
#pragma unroll
    for (int s = 0; s < STAGES - 1; s++) {
        load_stage(s, s);
        cp_commit();
    }

    int rs = 0, ws = STAGES - 1;
    for (int k = 0; k < NK; k++) {
        cp_wait<STAGES - 2>();
        __syncthreads();
        // issue next stage's loads BEFORE compute so DRAM overlaps the MMA block
        if (k + STAGES - 1 < NK) load_stage(ws, k + STAGES - 1);
        cp_commit();
        compute_stage(rs);
        if (++rs == STAGES) rs = 0;
        if (++ws == STAGES) ws = 0;
    }

    // epilogue: (acc + bias) * scale, float2 stores
#pragma unroll
    for (int nf = 0; nf < 8; nf++) {
        int n0 = nb + warp_n + nf * 8 + 2 * (lane & 3);
        float s0 = scale[n0], s1 = scale[n0 + 1];
        float b0 = bias[n0], b1 = bias[n0 + 1];
#pragma unroll
        for (int mt = 0; mt < 2; mt++) {
            int m0 = mb + warp_m + mt * 16 + (lane >> 2);
            float* p0 = out + (size_t)m0 * OUT_DIM + n0;
            float2 v0;
            v0.x = (acc[mt][nf][0] + b0) * s0;
            v0.y = (acc[mt][nf][1] + b1) * s1;
            *(float2*)p0 = v0;
            float2 v1;
            v1.x = (acc[mt][nf][2] + b0) * s0;
            v1.y = (acc[mt][nf][3] + b1) * s1;
            *(float2*)(p0 + 8 * OUT_DIM) = v1;
        }
    }
}

// ---------------- launch ----------------
extern "C" void kernel_launch(void* const* d_in, const int* in_sizes, int n_in,
                              void* d_out, int out_size) {
    const float* x      = (const float*)d_in[0];
    const int*   stored = (const int*)d_in[1];
    const int*   sgn    = (const int*)d_in[2];
    const float* lmin   = (const float*)d_in[3];
    const float* lmax   = (const float*)d_in[4];
    const float* scale  = (const float*)d_in[5];
    const float* bias   = (const float*)d_in[6];
    float* out = (float*)d_out;

    dequant_kernel<<<4096, 256>>>(stored, sgn, lmin, lmax);
    xsplit_kernel<<<512, 256>>>(x);

    static int smem_set = 0;
    if (!smem_set) {
        cudaFuncSetAttribute(gemm_kernel, cudaFuncAttributeMaxDynamicSharedMemorySize, SMEM_TOTAL);
        smem_set = 1;
    }
    dim3 grid(OUT_DIM / BN, B_DIM / BM);   // (86, 4)
    gemm_kernel<<<grid, THREADS, SMEM_TOTAL>>>(out, scale, bias);
}

// round 6
// speedup vs baseline: 1.5075x; 1.5075x over previous
#include <cuda_runtime.h>
#include <cuda_fp16.h>
#include <cstdint>

#define B_DIM   512
#define IN_DIM  4096
#define OUT_DIM 11008

#define BM 128
#define BN 128
#define BK 32
#define NK (IN_DIM / BK)   // 128 k-chunks
#define STAGES 4
#define THREADS 256

#define ROWPAD 80                       // 64B data + 16B pad per row (bank-conflict-free)
#define TILE_B (128 * ROWPAD)           // 10240 B per tile
#define STAGE_B (3 * TILE_B)            // 30720 B per stage (Ahi, Alo, Bw)
#define SMEM_TOTAL (STAGES * STAGE_B)   // 122880 B

// ---------------- device scratch (static device arrays are allowed) ----------------
__device__ __half g_w[(size_t)OUT_DIM * IN_DIM];
__device__ __half g_xhi[(size_t)B_DIM * IN_DIM];
__device__ __half g_xlo[(size_t)B_DIM * IN_DIM];

// ---------------- PTX helpers (plain sm_80+ features only) -------------------------
__device__ __forceinline__ uint32_t smem_u32(const void* p) {
    uint32_t a;
    asm("{ .reg .u64 t; cvta.to.shared.u64 t, %1; cvt.u32.u64 %0, t; }" : "=r"(a) : "l"(p));
    return a;
}

__device__ __forceinline__ void cp16(uint32_t s, const void* g) {
    asm volatile("cp.async.cg.shared.global [%0], [%1], 16;" :: "r"(s), "l"(g));
}
__device__ __forceinline__ void cp_commit() {
    asm volatile("cp.async.commit_group;" ::: "memory");
}
template <int N>
__device__ __forceinline__ void cp_wait() {
    asm volatile("cp.async.wait_group %0;" :: "n"(N) : "memory");
}

__device__ __forceinline__ void ldsm4(uint32_t* r, uint32_t addr) {
    asm volatile("ldmatrix.sync.aligned.m8n8.x4.shared.b16 {%0,%1,%2,%3}, [%4];"
                 : "=r"(r[0]), "=r"(r[1]), "=r"(r[2]), "=r"(r[3]) : "r"(addr));
}

__device__ __forceinline__ void mma_fp16(float* d, const uint32_t* a, const uint32_t* b) {
    asm volatile("mma.sync.aligned.m16n8k16.row.col.f32.f16.f16.f32 "
                 "{%0,%1,%2,%3}, {%4,%5,%6,%7}, {%8,%9}, {%0,%1,%2,%3};"
                 : "+f"(d[0]), "+f"(d[1]), "+f"(d[2]), "+f"(d[3])
                 : "r"(a[0]), "r"(a[1]), "r"(a[2]), "r"(a[3]), "r"(b[0]), "r"(b[1]));
}

// ---------------- Kernel 1: dequant W -> single fp16 (256-entry exp LUT) -----------
__global__ void dequant_kernel(const int* __restrict__ stored, const int* __restrict__ sgn,
                               const float* __restrict__ lmin_p, const float* __restrict__ lmax_p) {
    __shared__ unsigned short lut[256];
    float lmin = *lmin_p;
    float kf = (*lmax_p - lmin) * (1.0f / 254.0f);
    for (int s = threadIdx.x; s < 256; s += blockDim.x) {
        float w = expf(lmin + (float)(255 - s) * kf);
        lut[s] = __half_as_ushort(__float2half_rn(w));
    }
    __syncthreads();

    const int4* st4 = (const int4*)stored;
    const int4* sg4 = (const int4*)sgn;
    ushort4* w4 = (ushort4*)g_w;
    size_t nq = (size_t)OUT_DIM * IN_DIM / 4;
    for (size_t i = (size_t)blockIdx.x * blockDim.x + threadIdx.x; i < nq;
         i += (size_t)gridDim.x * blockDim.x) {
        int4 s = st4[i];
        int4 g = sg4[i];
        unsigned short h0 = lut[s.x & 255] ^ (g.x < 0 ? 0x8000u : 0u);
        unsigned short h1 = lut[s.y & 255] ^ (g.y < 0 ? 0x8000u : 0u);
        unsigned short h2 = lut[s.z & 255] ^ (g.z < 0 ? 0x8000u : 0u);
        unsigned short h3 = lut[s.w & 255] ^ (g.w < 0 ? 0x8000u : 0u);
        w4[i] = make_ushort4(h0, h1, h2, h3);
    }
}

// ---------------- Kernel 2: split x -> fp16 hi/lo ----------------------------------
__global__ void xsplit_kernel(const float* __restrict__ x) {
    const float4* x4 = (const float4*)x;
    ushort4* xh = (ushort4*)g_xhi;
    ushort4* xl = (ushort4*)g_xlo;
    size_t n4 = (size_t)B_DIM * IN_DIM / 4;
    for (size_t i = (size_t)blockIdx.x * blockDim.x + threadIdx.x; i < n4;
         i += (size_t)gridDim.x * blockDim.x) {
        float4 v = x4[i];
        float vv[4] = {v.x, v.y, v.z, v.w};
        unsigned short h[4], l[4];
#pragma unroll
        for (int j = 0; j < 4; j++) {
            __half hb = __float2half_rn(vv[j]);
            float fh = __half2float(hb);
            h[j] = __half_as_ushort(hb);
            l[j] = __half_as_ushort(__float2half_rn(vv[j] - fh));
        }
        xh[i] = make_ushort4(h[0], h[1], h[2], h[3]);
        xl[i] = make_ushort4(l[0], l[1], l[2], l[3]);
    }
}

// ---------------- Kernel 3: pipelined mma.sync fp16 GEMM + epilogue ----------------
// 2-term split: y = x_hi*w + x_lo*w   (w single fp16; x exact to ~2^-22)
__global__ void __launch_bounds__(THREADS, 1)
gemm_kernel(float* __restrict__ out, const float* __restrict__ scale,
            const float* __restrict__ bias) {
    extern __shared__ char smem[];
    const uint32_t sb = smem_u32(smem);
    const int tid = threadIdx.x;
    const int lane = tid & 31, wid = tid >> 5;
    const int nb = blockIdx.x * BN, mb = blockIdx.y * BM;
    const int warp_m = (wid & 3) * 32, warp_n = (wid >> 2) * 64;

    const char* gAh = (const char*)(g_xhi + (size_t)mb * IN_DIM);
    const char* gAl = (const char*)(g_xlo + (size_t)mb * IN_DIM);
    const char* gBw = (const char*)(g_w + (size_t)nb * IN_DIM);

    // cp.async mapping: thread -> (row = tid/2, 32B half = tid%2); 2x16B per tile
    const int lrow = tid >> 1;
    const int lc = (tid & 1) * 32;

    // ldmatrix base offsets
    const uint32_t a_off = (uint32_t)(warp_m + (lane & 15)) * ROWPAD + ((lane >> 4) * 16);
    const uint32_t b_off =
        (uint32_t)(warp_n + (lane & 7) + ((lane >> 4) & 1) * 8) * ROWPAD + (((lane >> 3) & 1) * 16);

    float acc[2][8][4];
#pragma unroll
    for (int i = 0; i < 2; i++)
#pragma unroll
        for (int j = 0; j < 8; j++)
#pragma unroll
            for (int c = 0; c < 4; c++) acc[i][j][c] = 0.0f;

    auto load_stage = [&](int s, int k) {
        size_t go = (size_t)lrow * (IN_DIM * 2) + (size_t)k * (BK * 2) + lc;
        uint32_t so = sb + s * STAGE_B + (uint32_t)lrow * ROWPAD + lc;
        cp16(so, gAh + go);
        cp16(so + 16, gAh + go + 16);
        cp16(so + TILE_B, gAl + go);
        cp16(so + TILE_B + 16, gAl + go + 16);
        cp16(so + 2 * TILE_B, gBw + go);
        cp16(so + 2 * TILE_B + 16, gBw + go + 16);
    };

    auto compute_stage = [&](int s) {
        uint32_t st = sb + s * STAGE_B;
        uint32_t aH = st + a_off, aL = st + TILE_B + a_off;
        uint32_t bW = st + 2 * TILE_B + b_off;
#pragma unroll
        for (int s16 = 0; s16 < 2; s16++) {
            uint32_t kb = s16 * 32;
            uint32_t ah[2][4], al[2][4];
            ldsm4(ah[0], aH + kb);
            ldsm4(ah[1], aH + 16 * ROWPAD + kb);
            ldsm4(al[0], aL + kb);
            ldsm4(al[1], aL + 16 * ROWPAD + kb);
#pragma unroll
            for (int nblk = 0; nblk < 4; nblk++) {
                uint32_t bw[4];
                ldsm4(bw, bW + nblk * 16 * ROWPAD + kb);
#pragma unroll
                for (int mt = 0; mt < 2; mt++) {
                    mma_fp16(acc[mt][2 * nblk], ah[mt], bw);
                    mma_fp16(acc[mt][2 * nblk], al[mt], bw);
                    mma_fp16(acc[mt][2 * nblk + 1], ah[mt], bw + 2);
                    mma_fp16(acc[mt][2 * nblk + 1], al[mt], bw + 2);
                }
            }
        }
    };

    // prologue: fill STAGES-1 stages
#pragma unroll
    for (int s = 0; s < STAGES - 1; s++) {
        load_stage(s, s);
        cp_commit();
    }

    int rs = 0, ws = STAGES - 1;
    for (int k = 0; k < NK; k++) {
        cp_wait<STAGES - 2>();
        __syncthreads();
        compute_stage(rs);
        if (k + STAGES - 1 < NK) load_stage(ws, k + STAGES - 1);
        cp_commit();
        rs = (rs + 1) & (STAGES - 1);
        ws = (ws + 1) & (STAGES - 1);
    }

    // epilogue: (acc + bias) * scale, float2 stores
#pragma unroll
    for (int nf = 0; nf < 8; nf++) {
        int n0 = nb + warp_n + nf * 8 + 2 * (lane & 3);
        float s0 = scale[n0], s1 = scale[n0 + 1];
        float b0 = bias[n0], b1 = bias[n0 + 1];
#pragma unroll
        for (int mt = 0; mt < 2; mt++) {
            int m0 = mb + warp_m + mt * 16 + (lane >> 2);
            float* p0 = out + (size_t)m0 * OUT_DIM + n0;
            float2 v0;
            v0.x = (acc[mt][nf][0] + b0) * s0;
            v0.y = (acc[mt][nf][1] + b1) * s1;
            *(float2*)p0 = v0;
            float2 v1;
            v1.x = (acc[mt][nf][2] + b0) * s0;
            v1.y = (acc[mt][nf][3] + b1) * s1;
            *(float2*)(p0 + 8 * OUT_DIM) = v1;
        }
    }
}

// ---------------- launch ----------------
extern "C" void kernel_launch(void* const* d_in, const int* in_sizes, int n_in,
                              void* d_out, int out_size) {
    const float* x      = (const float*)d_in[0];
    const int*   stored = (const int*)d_in[1];
    const int*   sgn    = (const int*)d_in[2];
    const float* lmin   = (const float*)d_in[3];
    const float* lmax   = (const float*)d_in[4];
    const float* scale  = (const float*)d_in[5];
    const float* bias   = (const float*)d_in[6];
    float* out = (float*)d_out;

    dequant_kernel<<<4096, 256>>>(stored, sgn, lmin, lmax);
    xsplit_kernel<<<512, 256>>>(x);

    static int smem_set = 0;
    if (!smem_set) {
        cudaFuncSetAttribute(gemm_kernel, cudaFuncAttributeMaxDynamicSharedMemorySize, SMEM_TOTAL);
        smem_set = 1;
    }
    dim3 grid(OUT_DIM / BN, B_DIM / BM);   // (86, 4)
    gemm_kernel<<<grid, THREADS, SMEM_TOTAL>>>(out, scale, bias);
}

// round 8
// speedup vs baseline: 2.4414x; 1.6194x over previous
#include <cuda_runtime.h>
#include <cuda_fp16.h>
#include <cstdint>

#define B_DIM   512
#define IN_DIM  4096
#define OUT_DIM 11008

#define BM 128
#define BN 128
#define BK 32
#define NK (IN_DIM / BK)   // 128 k-chunks
#define STAGES 4
#define THREADS 256

#define ROWPAD 80                       // 64B data + 16B pad per row (bank-conflict-free)
#define TILE_B (128 * ROWPAD)           // 10240 B per tile
#define STAGE_B (2 * TILE_B)            // 20480 B per stage (A, B)
#define SMEM_TOTAL (STAGES * STAGE_B)   // 81920 B

// ---------------- device scratch (static device arrays are allowed) ----------------
__device__ __half g_w[(size_t)OUT_DIM * IN_DIM];
__device__ __half g_x[(size_t)B_DIM * IN_DIM];

// ---------------- PTX helpers (plain sm_80+ features only) -------------------------
__device__ __forceinline__ uint32_t smem_u32(const void* p) {
    uint32_t a;
    asm("{ .reg .u64 t; cvta.to.shared.u64 t, %1; cvt.u32.u64 %0, t; }" : "=r"(a) : "l"(p));
    return a;
}

__device__ __forceinline__ void cp16(uint32_t s, const void* g) {
    asm volatile("cp.async.cg.shared.global [%0], [%1], 16;" :: "r"(s), "l"(g));
}
__device__ __forceinline__ void cp_commit() {
    asm volatile("cp.async.commit_group;" ::: "memory");
}
template <int N>
__device__ __forceinline__ void cp_wait() {
    asm volatile("cp.async.wait_group %0;" :: "n"(N) : "memory");
}

__device__ __forceinline__ void ldsm4(uint32_t* r, uint32_t addr) {
    asm volatile("ldmatrix.sync.aligned.m8n8.x4.shared.b16 {%0,%1,%2,%3}, [%4];"
                 : "=r"(r[0]), "=r"(r[1]), "=r"(r[2]), "=r"(r[3]) : "r"(addr));
}

__device__ __forceinline__ void mma_fp16(float* d, const uint32_t* a, const uint32_t* b) {
    asm volatile("mma.sync.aligned.m16n8k16.row.col.f32.f16.f16.f32 "
                 "{%0,%1,%2,%3}, {%4,%5,%6,%7}, {%8,%9}, {%0,%1,%2,%3};"
                 : "+f"(d[0]), "+f"(d[1]), "+f"(d[2]), "+f"(d[3])
                 : "r"(a[0]), "r"(a[1]), "r"(a[2]), "r"(a[3]), "r"(b[0]), "r"(b[1]));
}

// ---------------- Kernel 1: dequant W -> single fp16 (256-entry exp LUT) -----------
__global__ void dequant_kernel(const int* __restrict__ stored, const int* __restrict__ sgn,
                               const float* __restrict__ lmin_p, const float* __restrict__ lmax_p) {
    __shared__ unsigned short lut[256];
    float lmin = *lmin_p;
    float kf = (*lmax_p - lmin) * (1.0f / 254.0f);
    for (int s = threadIdx.x; s < 256; s += blockDim.x) {
        float w = expf(lmin + (float)(255 - s) * kf);
        lut[s] = __half_as_ushort(__float2half_rn(w));
    }
    __syncthreads();

    const int4* st4 = (const int4*)stored;
    const int4* sg4 = (const int4*)sgn;
    ushort4* w4 = (ushort4*)g_w;
    size_t nq = (size_t)OUT_DIM * IN_DIM / 4;
    for (size_t i = (size_t)blockIdx.x * blockDim.x + threadIdx.x; i < nq;
         i += (size_t)gridDim.x * blockDim.x) {
        int4 s = st4[i];
        int4 g = sg4[i];
        unsigned short h0 = lut[s.x & 255] ^ (g.x < 0 ? 0x8000u : 0u);
        unsigned short h1 = lut[s.y & 255] ^ (g.y < 0 ? 0x8000u : 0u);
        unsigned short h2 = lut[s.z & 255] ^ (g.z < 0 ? 0x8000u : 0u);
        unsigned short h3 = lut[s.w & 255] ^ (g.w < 0 ? 0x8000u : 0u);
        w4[i] = make_ushort4(h0, h1, h2, h3);
    }
}

// ---------------- Kernel 2: convert x -> fp16 --------------------------------------
__global__ void xconv_kernel(const float* __restrict__ x) {
    const float4* x4 = (const float4*)x;
    ushort4* xh = (ushort4*)g_x;
    size_t n4 = (size_t)B_DIM * IN_DIM / 4;
    for (size_t i = (size_t)blockIdx.x * blockDim.x + threadIdx.x; i < n4;
         i += (size_t)gridDim.x * blockDim.x) {
        float4 v = x4[i];
        xh[i] = make_ushort4(__half_as_ushort(__float2half_rn(v.x)),
                             __half_as_ushort(__float2half_rn(v.y)),
                             __half_as_ushort(__float2half_rn(v.z)),
                             __half_as_ushort(__float2half_rn(v.w)));
    }
}

// ---------------- Kernel 3: pipelined mma.sync fp16 GEMM + epilogue ----------------
__global__ void __launch_bounds__(THREADS, 1)
gemm_kernel(float* __restrict__ out, const float* __restrict__ scale,
            const float* __restrict__ bias) {
    extern __shared__ char smem[];
    const uint32_t sb = smem_u32(smem);
    const int tid = threadIdx.x;
    const int lane = tid & 31, wid = tid >> 5;
    const int nb = blockIdx.x * BN, mb = blockIdx.y * BM;
    const int warp_m = (wid & 3) * 32, warp_n = (wid >> 2) * 64;

    const char* gA = (const char*)(g_x + (size_t)mb * IN_DIM);
    const char* gB = (const char*)(g_w + (size_t)nb * IN_DIM);

    // cp.async mapping: thread -> (row = tid/2, 32B half = tid%2); 2x16B per tile
    const int lrow = tid >> 1;
    const int lc = (tid & 1) * 32;

    // ldmatrix base offsets
    const uint32_t a_off = (uint32_t)(warp_m + (lane & 15)) * ROWPAD + ((lane >> 4) * 16);
    const uint32_t b_off =
        (uint32_t)(warp_n + (lane & 7) + ((lane >> 4) & 1) * 8) * ROWPAD + (((lane >> 3) & 1) * 16);

    float acc[2][8][4];
#pragma unroll
    for (int i = 0; i < 2; i++)
#pragma unroll
        for (int j = 0; j < 8; j++)
#pragma unroll
            for (int c = 0; c < 4; c++) acc[i][j][c] = 0.0f;

    auto load_stage = [&](int s, int k) {
        size_t go = (size_t)lrow * (IN_DIM * 2) + (size_t)k * (BK * 2) + lc;
        uint32_t so = sb + s * STAGE_B + (uint32_t)lrow * ROWPAD + lc;
        cp16(so, gA + go);
        cp16(so + 16, gA + go + 16);
        cp16(so + TILE_B, gB + go);
        cp16(so + TILE_B + 16, gB + go + 16);
    };

    auto compute_stage = [&](int s) {
        uint32_t st = sb + s * STAGE_B;
        uint32_t aA = st + a_off;
        uint32_t bB = st + TILE_B + b_off;
#pragma unroll
        for (int s16 = 0; s16 < 2; s16++) {
            uint32_t kb = s16 * 32;
            uint32_t a[2][4];
            ldsm4(a[0], aA + kb);
            ldsm4(a[1], aA + 16 * ROWPAD + kb);
#pragma unroll
            for (int nblk = 0; nblk < 4; nblk++) {
                uint32_t b[4];
                ldsm4(b, bB + nblk * 16 * ROWPAD + kb);
#pragma unroll
                for (int mt = 0; mt < 2; mt++) {
                    mma_fp16(acc[mt][2 * nblk], a[mt], b);
                    mma_fp16(acc[mt][2 * nblk + 1], a[mt], b + 2);
                }
            }
        }
    };

    // prologue: fill STAGES-1 stages
#pragma unroll
    for (int s = 0; s < STAGES - 1; s++) {
        load_stage(s, s);
        cp_commit();
    }

    int rs = 0, ws = STAGES - 1;
    for (int k = 0; k < NK; k++) {
        cp_wait<STAGES - 2>();
        __syncthreads();
        compute_stage(rs);
        if (k + STAGES - 1 < NK) load_stage(ws, k + STAGES - 1);
        cp_commit();
        rs = (rs + 1) & (STAGES - 1);
        ws = (ws + 1) & (STAGES - 1);
    }

    // epilogue: (acc + bias) * scale, float2 stores
#pragma unroll
    for (int nf = 0; nf < 8; nf++) {
        int n0 = nb + warp_n + nf * 8 + 2 * (lane & 3);
        float s0 = scale[n0], s1 = scale[n0 + 1];
        float b0 = bias[n0], b1 = bias[n0 + 1];
#pragma unroll
        for (int mt = 0; mt < 2; mt++) {
            int m0 = mb + warp_m + mt * 16 + (lane >> 2);
            float* p0 = out + (size_t)m0 * OUT_DIM + n0;
            float2 v0;
            v0.x = (acc[mt][nf][0] + b0) * s0;
            v0.y = (acc[mt][nf][1] + b1) * s1;
            *(float2*)p0 = v0;
            float2 v1;
            v1.x = (acc[mt][nf][2] + b0) * s0;
            v1.y = (acc[mt][nf][3] + b1) * s1;
            *(float2*)(p0 + 8 * OUT_DIM) = v1;
        }
    }
}

// ---------------- launch ----------------
extern "C" void kernel_launch(void* const* d_in, const int* in_sizes, int n_in,
                              void* d_out, int out_size) {
    const float* x      = (const float*)d_in[0];
    const int*   stored = (const int*)d_in[1];
    const int*   sgn    = (const int*)d_in[2];
    const float* lmin   = (const float*)d_in[3];
    const float* lmax   = (const float*)d_in[4];
    const float* scale  = (const float*)d_in[5];
    const float* bias   = (const float*)d_in[6];
    float* out = (float*)d_out;

    dequant_kernel<<<4096, 256>>>(stored, sgn, lmin, lmax);
    xconv_kernel<<<512, 256>>>(x);

    static int smem_set = 0;
    if (!smem_set) {
        cudaFuncSetAttribute(gemm_kernel, cudaFuncAttributeMaxDynamicSharedMemorySize, SMEM_TOTAL);
        smem_set = 1;
    }
    dim3 grid(OUT_DIM / BN, B_DIM / BM);   // (86, 4)
    gemm_kernel<<<grid, THREADS, SMEM_TOTAL>>>(out, scale, bias);
}